// round 7
// baseline (speedup 1.0000x reference)
#include <cuda_runtime.h>

#define NN 50000
#define NE 800000
#define NDIM 128
#define HID 64
#define EDIM 16

// ---------------- scratch (device globals; no allocation allowed) ----------
__device__ __align__(16) float g_H[NN * HID];      // pre-aggregation features (x@W)
__device__ __align__(16) float g_Acc[NN * HID];    // aggregation accumulator
__device__ __align__(16) float g_h[NN * HID];      // post relu features
__device__ __align__(16) float g_AB[NN * 128];     // [A | B] per node for edge MLP
__device__ int   g_deg[NN];
__device__ float g_dinv[NN];

// ---------------- vector reduction helper ----------------------------------
__device__ __forceinline__ void red_add_v4(float* p, float4 v) {
    asm volatile("red.global.add.v4.f32 [%0], {%1,%2,%3,%4};"
                 :: "l"(p), "f"(v.x), "f"(v.y), "f"(v.z), "f"(v.w)
                 : "memory");
}

// ---------------- degree kernels -------------------------------------------
__global__ void k_deg_init(int* deg) {
    int i = blockIdx.x * blockDim.x + threadIdx.x;
    if (i < NN) deg[i] = 1;   // self-loop
}
__global__ void k_deg_count(const int* __restrict__ ei, int* deg) {
    int e = blockIdx.x * blockDim.x + threadIdx.x;
    if (e < NE) atomicAdd(&deg[ei[NE + e]], 1);
}
__global__ void k_deg_inv(const int* __restrict__ deg, float* dinv) {
    int i = blockIdx.x * blockDim.x + threadIdx.x;
    if (i < NN) dinv[i] = rsqrtf((float)deg[i]);
}

// ---------------- GEMM: Out[N, 64-col-block] = X[N,K] @ W[K,64] ------------
// block: 64 rows x 64 cols, 256 threads, 4x4 microtile, K chunked by 32.
template <int K>
__global__ void k_gemm64(const float* __restrict__ X, const float* __restrict__ W,
                         float* __restrict__ Out, int ldout, int colOff) {
    __shared__ float sX[32][65];   // [k][row], padded
    __shared__ float sW[32][64];   // [k][col]
    int t  = threadIdx.x;
    int br = blockIdx.x * 64;
    int tx = t & 15, ty = t >> 4;
    float acc[4][4] = {};

    for (int kc = 0; kc < K; kc += 32) {
        #pragma unroll
        for (int i = 0; i < 8; i++) {
            int e2 = t + i * 256;
            int r = e2 >> 5, kk = e2 & 31;
            int row = br + r;
            sX[kk][r] = (row < NN) ? X[row * K + kc + kk] : 0.f;
        }
        #pragma unroll
        for (int i = 0; i < 8; i++) {
            int e2 = t + i * 256;
            int c = e2 & 63, kk = e2 >> 6;
            sW[kk][c] = W[(kc + kk) * 64 + c];
        }
        __syncthreads();
        #pragma unroll
        for (int kk = 0; kk < 32; kk++) {
            float a[4], b[4];
            #pragma unroll
            for (int i2 = 0; i2 < 4; i2++) a[i2] = sX[kk][ty * 4 + i2];
            #pragma unroll
            for (int j = 0; j < 4; j++) b[j] = sW[kk][tx * 4 + j];
            #pragma unroll
            for (int i2 = 0; i2 < 4; i2++)
                #pragma unroll
                for (int j = 0; j < 4; j++)
                    acc[i2][j] += a[i2] * b[j];
        }
        __syncthreads();
    }
    #pragma unroll
    for (int i2 = 0; i2 < 4; i2++) {
        int row = br + ty * 4 + i2;
        if (row < NN) {
            float4 v = make_float4(acc[i2][0], acc[i2][1], acc[i2][2], acc[i2][3]);
            *(float4*)&Out[row * ldout + colOff + tx * 4] = v;
        }
    }
}

// ---------------- self-loop init: Acc = H * dinv^2 --------------------------
__global__ void k_self_init(const float* __restrict__ H, const float* __restrict__ dinv,
                            float* __restrict__ Acc) {
    int tid = blockIdx.x * blockDim.x + threadIdx.x;
    if (tid >= NN * 16) return;
    int i = tid >> 4, q = tid & 15;
    float d = dinv[i];
    float n = d * d;
    float4 v = *(const float4*)&H[i * HID + q * 4];
    v.x *= n; v.y *= n; v.z *= n; v.w *= n;
    *(float4*)&Acc[i * HID + q * 4] = v;
}

// ---------------- edge scatter: Acc[dst] += H[src] * dinv[s]*dinv[d] --------
// One thread per (edge, float4 chunk): vector load + one v4 RED.
__global__ void k_scatter(const float* __restrict__ H, const float* __restrict__ dinv,
                          const int* __restrict__ ei, float* __restrict__ Acc) {
    int tid = blockIdx.x * blockDim.x + threadIdx.x;
    if (tid >= NE * 16) return;
    int e = tid >> 4, q = tid & 15;
    int src = ei[e];
    int dst = ei[NE + e];
    float n = dinv[src] * dinv[dst];
    float4 v = *(const float4*)&H[src * HID + q * 4];
    v.x *= n; v.y *= n; v.z *= n; v.w *= n;
    red_add_v4(&Acc[dst * HID + q * 4], v);
}

// ---------------- bias + relu ----------------------------------------------
__global__ void k_bias_relu(const float* __restrict__ Acc, const float* __restrict__ b,
                            float* __restrict__ out) {
    int tid = blockIdx.x * blockDim.x + threadIdx.x;
    if (tid >= NN * HID) return;
    out[tid] = fmaxf(Acc[tid] + b[tid & 63], 0.f);
}

// ---------------- edge MLP: warp per edge ----------------------------------
__global__ void k_edge_mlp(const float* __restrict__ AB, const int* __restrict__ ei,
                           const float* __restrict__ attr, const float* __restrict__ Wm1,
                           const float* __restrict__ bm1, const float* __restrict__ Wm2,
                           const float* __restrict__ bm2, float* __restrict__ out) {
    __shared__ float sWe[EDIM][HID];   // Wm1 rows 128..143
    __shared__ float sW2[HID][2];
    __shared__ float sb1[HID];
    __shared__ float sb2[2];
    int t = threadIdx.x;
    const float* We = Wm1 + 128 * HID;
    for (int i = t; i < EDIM * HID; i += blockDim.x) ((float*)sWe)[i] = We[i];
    for (int i = t; i < HID * 2; i += blockDim.x)    ((float*)sW2)[i] = Wm2[i];
    if (t < HID) sb1[t] = bm1[t];
    if (t < 2)   sb2[t] = bm2[t];
    __syncthreads();

    int e = blockIdx.x * (blockDim.x >> 5) + (t >> 5);
    if (e >= NE) return;
    int l = t & 31;
    int src = ei[e];
    int dst = ei[NE + e];

    float a0 = AB[src * 128 + l];
    float a1 = AB[src * 128 + 32 + l];
    float b0 = AB[dst * 128 + 64 + l];
    float b1 = AB[dst * 128 + 96 + l];

    float av = (l < 16) ? attr[e * EDIM + l] : 0.f;
    float s0 = 0.f, s1 = 0.f;
    #pragma unroll
    for (int k = 0; k < EDIM; k++) {
        float ak = __shfl_sync(0xffffffffu, av, k);
        s0 += ak * sWe[k][l];
        s1 += ak * sWe[k][l + 32];
    }
    float e0 = fmaxf(a0 + b0 + s0 + sb1[l], 0.f);
    float e1 = fmaxf(a1 + b1 + s1 + sb1[l + 32], 0.f);

    float p0 = e0 * sW2[l][0] + e1 * sW2[l + 32][0];
    float p1 = e0 * sW2[l][1] + e1 * sW2[l + 32][1];
    #pragma unroll
    for (int off = 16; off; off >>= 1) {
        p0 += __shfl_xor_sync(0xffffffffu, p0, off);
        p1 += __shfl_xor_sync(0xffffffffu, p1, off);
    }
    if (l == 0) {
        out[e * 2]     = p0 + sb2[0];
        out[e * 2 + 1] = p1 + sb2[1];
    }
}

// ---------------- launch ----------------------------------------------------
extern "C" void kernel_launch(void* const* d_in, const int* in_sizes, int n_in,
                              void* d_out, int out_size) {
    const float* x    = (const float*)d_in[0];
    const int*   ei   = (const int*)d_in[1];     // edge_index is int32 (JAX x64 off)
    const float* attr = (const float*)d_in[2];
    const float* W1   = (const float*)d_in[3];
    const float* b1   = (const float*)d_in[4];
    const float* W2   = (const float*)d_in[5];
    const float* b2   = (const float*)d_in[6];
    const float* Wm1  = (const float*)d_in[7];
    const float* bm1  = (const float*)d_in[8];
    const float* Wm2  = (const float*)d_in[9];
    const float* bm2  = (const float*)d_in[10];
    float* out = (float*)d_out;

    float *H, *Acc, *h, *AB, *dinv; int* deg;
    cudaGetSymbolAddress((void**)&H,    g_H);
    cudaGetSymbolAddress((void**)&Acc,  g_Acc);
    cudaGetSymbolAddress((void**)&h,    g_h);
    cudaGetSymbolAddress((void**)&AB,   g_AB);
    cudaGetSymbolAddress((void**)&deg,  g_deg);
    cudaGetSymbolAddress((void**)&dinv, g_dinv);

    const int T = 256;
    int gb_nodes  = (NN + T - 1) / T;
    int gb_edges  = (NE + T - 1) / T;
    int gb_nv4    = (NN * 16 + T - 1) / T;
    int gb_ev4    = (NE * 16 + T - 1) / T;
    int gb_feat   = (NN * HID + T - 1) / T;
    int gb_gemm   = (NN + 63) / 64;
    int gb_emlp   = (NE + 7) / 8;

    // degrees (recomputed every call; deterministic)
    k_deg_init<<<gb_nodes, T>>>(deg);
    k_deg_count<<<gb_edges, T>>>(ei, deg);
    k_deg_inv<<<gb_nodes, T>>>(deg, dinv);

    // ---- GCN layer 1 ----
    k_gemm64<NDIM><<<gb_gemm, T>>>(x, W1, H, HID, 0);
    k_self_init<<<gb_nv4, T>>>(H, dinv, Acc);
    k_scatter<<<gb_ev4, T>>>(H, dinv, ei, Acc);
    k_bias_relu<<<gb_feat, T>>>(Acc, b1, h);

    // ---- GCN layer 2 ----
    k_gemm64<HID><<<gb_gemm, T>>>(h, W2, H, HID, 0);
    k_self_init<<<gb_nv4, T>>>(H, dinv, Acc);
    k_scatter<<<gb_ev4, T>>>(H, dinv, ei, Acc);
    k_bias_relu<<<gb_feat, T>>>(Acc, b2, h);

    // ---- per-node edge-MLP partials: A = h2@Wm1[0:64], B = h2@Wm1[64:128] ----
    k_gemm64<HID><<<gb_gemm, T>>>(h, Wm1,            AB, 128, 0);
    k_gemm64<HID><<<gb_gemm, T>>>(h, Wm1 + 64 * 64,  AB, 128, 64);

    // ---- edge MLP ----
    k_edge_mlp<<<gb_emlp, T>>>(AB, ei, attr, Wm1, bm1, Wm2, bm2, out);
}